// round 1
// baseline (speedup 1.0000x reference)
#include <cuda_runtime.h>
#include <cstdint>

#define B_DIM 128
#define N_DIM 256
#define RSM   208                 // P rows kept in shared memory
#define NGR   (N_DIM - RSM)       // 48 rows spilled to global (L2-resident)
#define ITERS 50

__device__ int   g_shift;         // y_true.max() + y_true.min()
__device__ __align__(16) float g_Pg[(size_t)B_DIM * NGR * N_DIM];  // 6.29 MB scratch
__device__ float g_ndcg[B_DIM];
__device__ int   g_valid[B_DIM];

// ---------------------------------------------------------------- min/max ---
__global__ void minmax_kernel(const int* __restrict__ t, int n) {
    __shared__ int smx[8], smn[8];
    int tid = threadIdx.x;
    int mx = -2147483647, mn = 2147483647;
    for (int i = tid; i < n; i += blockDim.x) { int x = t[i]; mx = max(mx, x); mn = min(mn, x); }
    for (int o = 16; o; o >>= 1) {
        mx = max(mx, __shfl_xor_sync(0xffffffffu, mx, o));
        mn = min(mn, __shfl_xor_sync(0xffffffffu, mn, o));
    }
    if ((tid & 31) == 0) { smx[tid >> 5] = mx; smn[tid >> 5] = mn; }
    __syncthreads();
    if (tid == 0) {
        for (int k = 1; k < 8; k++) { mx = max(mx, smx[k]); mn = min(mn, smn[k]); }
        g_shift = mx + mn;
    }
}

// ------------------------------------------------------------- mega kernel ---
// One CTA per batch. Shared memory: P[0:RSM] + s, Bm, gains, u, v, w, ei, red.
__global__ void __launch_bounds__(256, 1)
mega_kernel(const float* __restrict__ yp, const int* __restrict__ ytr) {
    extern __shared__ float sm[];
    float* Ps  = sm;                       // RSM * 256
    float* s   = Ps + RSM * N_DIM;
    float* Bm  = s  + N_DIM;
    float* gA  = Bm + N_DIM;
    float* u   = gA + N_DIM;
    float* v   = u  + N_DIM;
    float* w   = v  + N_DIM;
    int*   ei  = (int*)(w + N_DIM);
    float* red = (float*)(ei + N_DIM);     // 32 floats

    const int b    = blockIdx.x;
    const int tid  = threadIdx.x;
    const int lane = tid & 31;
    const int wid  = tid >> 5;

    // ---- load, flipped relevancy, gains ----
    float sj = yp[b * N_DIM + tid];
    s[tid] = sj;
    int e = g_shift - ytr[b * N_DIM + tid];
    e = min(max(e, 0), 30);
    ei[tid] = e;
    float gain = (float)((1u << e) - 1u);   // 2^yt - 1, exact
    gA[tid] = gain;
    u[tid] = 1.0f;
    __syncthreads();

    // ---- B_mat[j] = sum_k |s_j - s_k| (Kahan) ----
    float bsum = 0.f, bc = 0.f;
    for (int k = 0; k < N_DIM; k++) {
        float d  = fabsf(sj - s[k]);
        float y  = d - bc;
        float t2 = bsum + y;
        bc = (t2 - bsum) - y;
        bsum = t2;
    }
    Bm[tid] = bsum;

    // ---- IDCG via stable rank (ties share equal gain -> order irrelevant) ----
    int pos = 0;
    for (int k = 0; k < N_DIM; k++) {
        int ek = ei[k];
        pos += (ek > e) ? 1 : 0;
        pos += ((k < tid) && (ek == e)) ? 1 : 0;
    }
    float term = gain / log2f((float)(pos + 2));
    float x = term;
    for (int o = 16; o; o >>= 1) x += __shfl_xor_sync(0xffffffffu, x, o);
    if (lane == 0) red[wid] = x;
    __syncthreads();   // also publishes Bm[]
    if (wid == 0) {
        float y2 = (lane < 8) ? red[lane] : 0.f;
        for (int o = 4; o; o >>= 1) y2 += __shfl_xor_sync(0xffffffffu, y2, o);
        if (lane == 0) red[0] = y2;
    }
    __syncthreads();
    const float idcg = red[0];

    // ---- build P: row i = softmax_j(s_j*(255-2i) - Bm_j)  (tau = 1) ----
    float* gp = g_Pg + (size_t)b * NGR * N_DIM;
    for (int i = wid; i < N_DIM; i += 8) {
        float sc = (float)(255 - 2 * i);
        float lg[8], ev[8];
        float mx = -3.4e38f;
        #pragma unroll
        for (int k = 0; k < 8; k++) {
            int j = k * 32 + lane;
            float l = s[j] * sc - Bm[j];
            lg[k] = l;
            mx = fmaxf(mx, l);
        }
        for (int o = 16; o; o >>= 1) mx = fmaxf(mx, __shfl_xor_sync(0xffffffffu, mx, o));
        float ssum = 0.f;
        #pragma unroll
        for (int k = 0; k < 8; k++) { float ex = expf(lg[k] - mx); ev[k] = ex; ssum += ex; }
        for (int o = 16; o; o >>= 1) ssum += __shfl_xor_sync(0xffffffffu, ssum, o);
        float inv = 1.0f / ssum;
        if (i < RSM) {
            float* row = Ps + i * N_DIM;
            #pragma unroll
            for (int k = 0; k < 8; k++) row[k * 32 + lane] = ev[k] * inv;
        } else {
            float* row = gp + (i - RSM) * N_DIM;
            #pragma unroll
            for (int k = 0; k < 8; k++) row[k * 32 + lane] = ev[k] * inv;
        }
    }
    __syncthreads();   // orders smem AND our global P writes within the block

    // ---- 50 Sinkhorn iterations on diagonal scalings (u, v) ----
    for (int it = 0; it < ITERS; it++) {
        // column pass: S_j = sum_i P[i][j] * u[i]   (thread == column, conflict-free)
        float a0 = 0.f, a1 = 0.f, a2 = 0.f, a3 = 0.f;
        {
            const float* gcol = gp + tid;           // L2-resident rows first (MLP)
            #pragma unroll 4
            for (int i4 = 0; i4 < NGR / 4; i4++) {
                float4 uu = *(const float4*)(u + RSM + i4 * 4);
                a0 += gcol[(i4 * 4 + 0) * N_DIM] * uu.x;
                a1 += gcol[(i4 * 4 + 1) * N_DIM] * uu.y;
                a2 += gcol[(i4 * 4 + 2) * N_DIM] * uu.z;
                a3 += gcol[(i4 * 4 + 3) * N_DIM] * uu.w;
            }
            const float* col = Ps + tid;
            #pragma unroll 4
            for (int i4 = 0; i4 < RSM / 4; i4++) {
                float4 uu = *(const float4*)(u + i4 * 4);
                a0 += col[(i4 * 4 + 0) * N_DIM] * uu.x;
                a1 += col[(i4 * 4 + 1) * N_DIM] * uu.y;
                a2 += col[(i4 * 4 + 2) * N_DIM] * uu.z;
                a3 += col[(i4 * 4 + 3) * N_DIM] * uu.w;
            }
        }
        float acc = (a0 + a1) + (a2 + a3);
        v[tid] = 1.0f / fmaxf(acc, 1e-10f);
        __syncthreads();

        // row pass: T_i = sum_j P[i][j] * v[j]   (warp per row, float4 + shfl)
        float4 va = *(const float4*)(v + 4 * lane);
        float4 vb = *(const float4*)(v + 128 + 4 * lane);
        for (int i = wid; i < N_DIM; i += 8) {
            float4 pa, pb;
            if (i < RSM) {
                const float4* row = (const float4*)(Ps + i * N_DIM);
                pa = row[lane]; pb = row[lane + 32];
            } else {
                const float4* row = (const float4*)(gp + (i - RSM) * N_DIM);
                pa = row[lane]; pb = row[lane + 32];
            }
            float acc2 = pa.x * va.x + pa.y * va.y + pa.z * va.z + pa.w * va.w
                       + pb.x * vb.x + pb.y * vb.y + pb.z * vb.z + pb.w * vb.w;
            for (int o = 16; o; o >>= 1) acc2 += __shfl_xor_sync(0xffffffffu, acc2, o);
            if (lane == 0) u[i] = 1.0f / fmaxf(acc2, 1e-10f);
        }
        __syncthreads();
    }

    // ---- final contraction: num = sum_i disc_i * u_i * sum_j P_ij * v_j * g_j ----
    w[tid] = v[tid] * gA[tid];
    __syncthreads();
    float4 wa = *(const float4*)(w + 4 * lane);
    float4 wb = *(const float4*)(w + 128 + 4 * lane);
    float part = 0.f;
    for (int i = wid; i < N_DIM; i += 8) {
        float4 pa, pb;
        if (i < RSM) {
            const float4* row = (const float4*)(Ps + i * N_DIM);
            pa = row[lane]; pb = row[lane + 32];
        } else {
            const float4* row = (const float4*)(gp + (i - RSM) * N_DIM);
            pa = row[lane]; pb = row[lane + 32];
        }
        float dot = pa.x * wa.x + pa.y * wa.y + pa.z * wa.z + pa.w * wa.w
                  + pb.x * wb.x + pb.y * wb.y + pb.z * wb.z + pb.w * wb.w;
        for (int o = 16; o; o >>= 1) dot += __shfl_xor_sync(0xffffffffu, dot, o);
        if (lane == 0) part += (u[i] / log2f((float)(i + 2))) * dot;
    }
    if (lane == 0) red[wid] = part;
    __syncthreads();
    if (tid == 0) {
        float num = 0.f;
        for (int k = 0; k < 8; k++) num += red[k];
        bool valid = (idcg != 0.0f);
        g_ndcg[b]  = valid ? (num / (idcg + 1e-10f)) : 0.0f;
        g_valid[b] = valid ? 1 : 0;
    }
}

// ---------------------------------------------------------------- finalize ---
__global__ void final_kernel(float* __restrict__ out) {
    int tid = threadIdx.x;           // 128 threads
    __shared__ float rs[4];
    __shared__ int   rc[4];
    float x = g_ndcg[tid];
    int   c = g_valid[tid];
    for (int o = 16; o; o >>= 1) {
        x += __shfl_xor_sync(0xffffffffu, x, o);
        c += __shfl_xor_sync(0xffffffffu, c, o);
    }
    int lane = tid & 31, wid = tid >> 5;
    if (lane == 0) { rs[wid] = x; rc[wid] = c; }
    __syncthreads();
    if (tid == 0) {
        float sum = 0.f; int cnt = 0;
        for (int k = 0; k < 4; k++) { sum += rs[k]; cnt += rc[k]; }
        out[0] = (cnt > 0) ? (-(sum / (float)cnt)) : 0.0f;
    }
}

// ------------------------------------------------------------------ launch ---
extern "C" void kernel_launch(void* const* d_in, const int* in_sizes, int n_in,
                              void* d_out, int out_size) {
    const float* yp  = (const float*)d_in[0];
    const int*   ytr = (const int*)d_in[1];
    float*       out = (float*)d_out;

    size_t smem = (size_t)(RSM * N_DIM + 7 * N_DIM + 32) * sizeof(float);  // 220288 B
    cudaFuncSetAttribute(mega_kernel, cudaFuncAttributeMaxDynamicSharedMemorySize, (int)smem);

    minmax_kernel<<<1, 256>>>(ytr, B_DIM * N_DIM);
    mega_kernel<<<B_DIM, 256, smem>>>(yp, ytr);
    final_kernel<<<1, 128>>>(out);
}

// round 2
// speedup vs baseline: 3.7160x; 3.7160x over previous
#include <cuda_runtime.h>
#include <cuda_fp16.h>

#define B_DIM 128
#define N_DIM 256
#define RSW   129                  // row stride in 32-bit words (128 half2 + 1 pad)
#define ITERS 50

__device__ unsigned g_mm[2];       // [0]=max key, [1]=min key (order-preserving unsigned)
__device__ float g_ndcg[B_DIM];
__device__ int   g_valid[B_DIM];

// ---------------------------------------------------------------- min/max ---
// 32 CTAs x 256 threads, one int4 each; CTA-reduce then 2 atomics per CTA.
__global__ void minmax_kernel(const int4* __restrict__ t4) {
    __shared__ unsigned smx[8], smn[8];
    int gid = blockIdx.x * 256 + threadIdx.x;
    int4 x = t4[gid];
    unsigned u0 = (unsigned)x.x ^ 0x80000000u;
    unsigned u1 = (unsigned)x.y ^ 0x80000000u;
    unsigned u2 = (unsigned)x.z ^ 0x80000000u;
    unsigned u3 = (unsigned)x.w ^ 0x80000000u;
    unsigned umx = max(max(u0, u1), max(u2, u3));
    unsigned umn = max(max(~u0, ~u1), max(~u2, ~u3));
    for (int o = 16; o; o >>= 1) {
        umx = max(umx, __shfl_xor_sync(0xffffffffu, umx, o));
        umn = max(umn, __shfl_xor_sync(0xffffffffu, umn, o));
    }
    int lane = threadIdx.x & 31, wid = threadIdx.x >> 5;
    if (lane == 0) { smx[wid] = umx; smn[wid] = umn; }
    __syncthreads();
    if (threadIdx.x == 0) {
        for (int k = 1; k < 8; k++) { umx = max(umx, smx[k]); umn = max(umn, smn[k]); }
        atomicMax(&g_mm[0], umx);
        atomicMax(&g_mm[1], umn);
    }
}

// ------------------------------------------------------------- mega kernel ---
// One CTA per batch, 256 threads. P stored fp16 in smem, padded rows (129 words)
// -> conflict-free column AND row access. Sinkhorn on diagonal scalings (u,v),
// both passes thread-per-output, no shuffles in the hot loop.
__global__ void __launch_bounds__(256, 1)
mega_kernel(const float* __restrict__ yp, const int* __restrict__ ytr) {
    extern __shared__ unsigned smw[];
    unsigned* Ph = smw;                          // 256*129 words (fp16 P)
    float* s  = (float*)(Ph + N_DIM * RSW);
    float* Bm = s  + N_DIM;
    float* gA = Bm + N_DIM;
    float* u  = gA + N_DIM;
    float* v  = u  + N_DIM;
    float* w  = v  + N_DIM;
    float* sp = w  + N_DIM;                      // 512 column partials
    float* red = sp + 2 * N_DIM;                 // 32
    int*   ei  = (int*)(red + 32);               // 256

    const int b    = blockIdx.x;
    const int tid  = threadIdx.x;
    const int lane = tid & 31;
    const int wid  = tid >> 5;

    // decoded global shift = y_true.max() + y_true.min()
    const int mx = (int)(g_mm[0] ^ 0x80000000u);
    const int mn = (int)((~g_mm[1]) ^ 0x80000000u);
    const int shift = mx + mn;

    // ---- load, flipped relevancy, gains ----
    float sj = yp[b * N_DIM + tid];
    s[tid] = sj;
    int e = shift - ytr[b * N_DIM + tid];
    e = min(max(e, 0), 30);
    ei[tid] = e;
    float gain = (float)((1u << e) - 1u);
    gA[tid] = gain;
    u[tid] = 1.0f;
    __syncthreads();

    // ---- B_mat[j] = sum_k |s_j - s_k| (Kahan) ----
    float bsum = 0.f, bc = 0.f;
    for (int k = 0; k < N_DIM; k++) {
        float d  = fabsf(sj - s[k]);
        float y  = d - bc;
        float t2 = bsum + y;
        bc = (t2 - bsum) - y;
        bsum = t2;
    }
    Bm[tid] = bsum;

    // ---- IDCG via stable rank (ties share equal gain) ----
    int pos = 0;
    for (int k = 0; k < N_DIM; k++) {
        int ek = ei[k];
        pos += (ek > e) ? 1 : 0;
        pos += ((k < tid) && (ek == e)) ? 1 : 0;
    }
    float x = gain / log2f((float)(pos + 2));
    for (int o = 16; o; o >>= 1) x += __shfl_xor_sync(0xffffffffu, x, o);
    if (lane == 0) red[wid] = x;
    __syncthreads();   // also publishes Bm[]
    if (wid == 0) {
        float y2 = (lane < 8) ? red[lane] : 0.f;
        for (int o = 4; o; o >>= 1) y2 += __shfl_xor_sync(0xffffffffu, y2, o);
        if (lane == 0) red[0] = y2;
    }
    __syncthreads();
    const float idcg = red[0];

    // ---- build P (fp16): row i = softmax_j(s_j*(255-2i) - Bm_j), tau=1 ----
    __half* Phh = (__half*)Ph;
    for (int i = wid; i < N_DIM; i += 8) {
        float sc = (float)(255 - 2 * i);
        float lg[8], ev[8];
        float mxl = -3.4e38f;
        #pragma unroll
        for (int k = 0; k < 8; k++) {
            int j = k * 32 + lane;
            float l = fmaf(s[j], sc, -Bm[j]);
            lg[k] = l;
            mxl = fmaxf(mxl, l);
        }
        for (int o = 16; o; o >>= 1) mxl = fmaxf(mxl, __shfl_xor_sync(0xffffffffu, mxl, o));
        float ssum = 0.f;
        #pragma unroll
        for (int k = 0; k < 8; k++) { float ex = expf(lg[k] - mxl); ev[k] = ex; ssum += ex; }
        for (int o = 16; o; o >>= 1) ssum += __shfl_xor_sync(0xffffffffu, ssum, o);
        float inv = 1.0f / ssum;
        __half* row = Phh + i * (2 * RSW);
        #pragma unroll
        for (int k = 0; k < 8; k++) row[k * 32 + lane] = __float2half_rn(ev[k] * inv);
    }
    __syncthreads();

    // ---- 50 Sinkhorn iterations ----
    const int p = tid & 127;                 // column pair (covers cols 2p, 2p+1)
    const int h = tid >> 7;                  // row half: 0 -> rows 0..127, 1 -> 128..255
    const unsigned* colp = Ph + h * 128 * RSW + p;
    const float* ub = u + h * 128;
    float* spw = sp + h * 256 + 2 * p;
    const unsigned* rowp = Ph + tid * RSW;

    for (int it = 0; it < ITERS; it++) {
        // column pass: partial S over this thread's 128 rows for cols (2p, 2p+1)
        float a0 = 0.f, a1 = 0.f, a2 = 0.f, a3 = 0.f;
        #pragma unroll
        for (int i4 = 0; i4 < 32; i4++) {
            float4 uu = *(const float4*)(ub + 4 * i4);
            unsigned w0 = colp[(4 * i4 + 0) * RSW];
            unsigned w1 = colp[(4 * i4 + 1) * RSW];
            unsigned w2 = colp[(4 * i4 + 2) * RSW];
            unsigned w3 = colp[(4 * i4 + 3) * RSW];
            float2 f0 = __half22float2(*(__half2*)&w0);
            float2 f1 = __half22float2(*(__half2*)&w1);
            float2 f2 = __half22float2(*(__half2*)&w2);
            float2 f3 = __half22float2(*(__half2*)&w3);
            a0 = fmaf(f0.x, uu.x, a0); a1 = fmaf(f0.y, uu.x, a1);
            a2 = fmaf(f1.x, uu.y, a2); a3 = fmaf(f1.y, uu.y, a3);
            a0 = fmaf(f2.x, uu.z, a0); a1 = fmaf(f2.y, uu.z, a1);
            a2 = fmaf(f3.x, uu.w, a2); a3 = fmaf(f3.y, uu.w, a3);
        }
        *(float2*)spw = make_float2(a0 + a2, a1 + a3);
        __syncthreads();

        // v update: thread j
        float S = sp[tid] + sp[256 + tid];
        v[tid] = 1.0f / fmaxf(S, 1e-10f);
        __syncthreads();

        // row pass: thread i computes T_i = sum_j P[i][j] * v[j]
        float r0 = 0.f, r1 = 0.f, r2 = 0.f, r3 = 0.f;
        #pragma unroll
        for (int j4 = 0; j4 < 32; j4++) {
            float4 v0 = *(const float4*)(v + 8 * j4);
            float4 v1 = *(const float4*)(v + 8 * j4 + 4);
            unsigned w0 = rowp[4 * j4 + 0];
            unsigned w1 = rowp[4 * j4 + 1];
            unsigned w2 = rowp[4 * j4 + 2];
            unsigned w3 = rowp[4 * j4 + 3];
            float2 f0 = __half22float2(*(__half2*)&w0);
            float2 f1 = __half22float2(*(__half2*)&w1);
            float2 f2 = __half22float2(*(__half2*)&w2);
            float2 f3 = __half22float2(*(__half2*)&w3);
            r0 = fmaf(f0.x, v0.x, r0); r1 = fmaf(f0.y, v0.y, r1);
            r2 = fmaf(f1.x, v0.z, r2); r3 = fmaf(f1.y, v0.w, r3);
            r0 = fmaf(f2.x, v1.x, r0); r1 = fmaf(f2.y, v1.y, r1);
            r2 = fmaf(f3.x, v1.z, r2); r3 = fmaf(f3.y, v1.w, r3);
        }
        float T = (r0 + r1) + (r2 + r3);
        u[tid] = 1.0f / fmaxf(T, 1e-10f);
        __syncthreads();
    }

    // ---- final: num = sum_i disc_i * u_i * (P[i] . (v*g)) ----
    w[tid] = v[tid] * gA[tid];
    __syncthreads();
    float r0 = 0.f, r1 = 0.f, r2 = 0.f, r3 = 0.f;
    #pragma unroll
    for (int j4 = 0; j4 < 32; j4++) {
        float4 v0 = *(const float4*)(w + 8 * j4);
        float4 v1 = *(const float4*)(w + 8 * j4 + 4);
        unsigned w0 = rowp[4 * j4 + 0];
        unsigned w1 = rowp[4 * j4 + 1];
        unsigned w2 = rowp[4 * j4 + 2];
        unsigned w3 = rowp[4 * j4 + 3];
        float2 f0 = __half22float2(*(__half2*)&w0);
        float2 f1 = __half22float2(*(__half2*)&w1);
        float2 f2 = __half22float2(*(__half2*)&w2);
        float2 f3 = __half22float2(*(__half2*)&w3);
        r0 = fmaf(f0.x, v0.x, r0); r1 = fmaf(f0.y, v0.y, r1);
        r2 = fmaf(f1.x, v0.z, r2); r3 = fmaf(f1.y, v0.w, r3);
        r0 = fmaf(f2.x, v1.x, r0); r1 = fmaf(f2.y, v1.y, r1);
        r2 = fmaf(f3.x, v1.z, r2); r3 = fmaf(f3.y, v1.w, r3);
    }
    float val = u[tid] * ((r0 + r1) + (r2 + r3)) / log2f((float)(tid + 2));
    for (int o = 16; o; o >>= 1) val += __shfl_xor_sync(0xffffffffu, val, o);
    if (lane == 0) red[wid] = val;
    __syncthreads();
    if (tid == 0) {
        float num = 0.f;
        for (int k = 0; k < 8; k++) num += red[k];
        bool valid = (idcg != 0.0f);
        g_ndcg[b]  = valid ? (num / (idcg + 1e-10f)) : 0.0f;
        g_valid[b] = valid ? 1 : 0;
    }
}

// ---------------------------------------------------------------- finalize ---
__global__ void final_kernel(float* __restrict__ out) {
    int tid = threadIdx.x;           // 128 threads
    __shared__ float rs[4];
    __shared__ int   rc[4];
    float x = g_ndcg[tid];
    int   c = g_valid[tid];
    for (int o = 16; o; o >>= 1) {
        x += __shfl_xor_sync(0xffffffffu, x, o);
        c += __shfl_xor_sync(0xffffffffu, c, o);
    }
    int lane = tid & 31, wid = tid >> 5;
    if (lane == 0) { rs[wid] = x; rc[wid] = c; }
    __syncthreads();
    if (tid == 0) {
        float sum = 0.f; int cnt = 0;
        for (int k = 0; k < 4; k++) { sum += rs[k]; cnt += rc[k]; }
        out[0] = (cnt > 0) ? (-(sum / (float)cnt)) : 0.0f;
    }
}

// ------------------------------------------------------------------ launch ---
extern "C" void kernel_launch(void* const* d_in, const int* in_sizes, int n_in,
                              void* d_out, int out_size) {
    const float* yp  = (const float*)d_in[0];
    const int*   ytr = (const int*)d_in[1];
    float*       out = (float*)d_out;

    void* mm_addr = nullptr;
    cudaGetSymbolAddress(&mm_addr, g_mm);
    cudaMemsetAsync(mm_addr, 0, 2 * sizeof(unsigned));

    size_t smem = (size_t)(N_DIM * RSW + 6 * N_DIM + 2 * N_DIM + 32 + N_DIM) * 4;  // 141440 B
    cudaFuncSetAttribute(mega_kernel, cudaFuncAttributeMaxDynamicSharedMemorySize, (int)smem);

    minmax_kernel<<<32, 256>>>((const int4*)ytr);
    mega_kernel<<<B_DIM, 256, smem>>>(yp, ytr);
    final_kernel<<<1, 128>>>(out);
}

// round 3
// speedup vs baseline: 3.7805x; 1.0173x over previous
#include <cuda_runtime.h>
#include <cuda_fp16.h>

#define B_DIM 128
#define N_DIM 256
#define RSW   129                  // P row stride in 32-bit words (128 half2 + 1 pad)
#define ITERS 50
#define NTHR  512

__device__ unsigned g_mm[2];       // [0]=max key, [1]=min key (order-preserving unsigned)
__device__ float g_ndcg[B_DIM];
__device__ int   g_valid[B_DIM];

// ---------------------------------------------------------------- min/max ---
__global__ void minmax_kernel(const int4* __restrict__ t4) {
    __shared__ unsigned smx[8], smn[8];
    int gid = blockIdx.x * 256 + threadIdx.x;
    int4 x = t4[gid];
    unsigned u0 = (unsigned)x.x ^ 0x80000000u;
    unsigned u1 = (unsigned)x.y ^ 0x80000000u;
    unsigned u2 = (unsigned)x.z ^ 0x80000000u;
    unsigned u3 = (unsigned)x.w ^ 0x80000000u;
    unsigned umx = max(max(u0, u1), max(u2, u3));
    unsigned umn = max(max(~u0, ~u1), max(~u2, ~u3));
    for (int o = 16; o; o >>= 1) {
        umx = max(umx, __shfl_xor_sync(0xffffffffu, umx, o));
        umn = max(umn, __shfl_xor_sync(0xffffffffu, umn, o));
    }
    int lane = threadIdx.x & 31, wid = threadIdx.x >> 5;
    if (lane == 0) { smx[wid] = umx; smn[wid] = umn; }
    __syncthreads();
    if (threadIdx.x == 0) {
        for (int k = 1; k < 8; k++) { umx = max(umx, smx[k]); umn = max(umn, smn[k]); }
        atomicMax(&g_mm[0], umx);
        atomicMax(&g_mm[1], umn);
    }
}

// ------------------------------------------------------------- mega kernel ---
// One CTA per batch, 512 threads (16 warps). P fp16 in smem, padded rows.
// Sinkhorn on diagonal scalings (u,v); column pass = thread-per-column-pair over
// 64 rows; row pass = thread-per-half-row; fp32 math; early exit on v-convergence.
__global__ void __launch_bounds__(NTHR, 1)
mega_kernel(const float* __restrict__ yp, const int* __restrict__ ytr) {
    extern __shared__ unsigned smw[];
    unsigned* Ph = smw;                          // 256*129 words (fp16 P)
    float* s   = (float*)(Ph + N_DIM * RSW);
    float* Bm  = s   + N_DIM;
    float* gA  = Bm  + N_DIM;
    float* u   = gA  + N_DIM;
    float* v   = u   + N_DIM;
    float* w   = v   + N_DIM;
    float* sp4 = w   + N_DIM;                    // 1024 column partials (4 quarters)
    float* rp  = sp4 + 4 * N_DIM;                // 512 row partials
    float* red = rp  + NTHR;                     // 32
    int*   ei  = (int*)(red + 32);               // 256

    const int tid  = threadIdx.x;
    const int b    = blockIdx.x;
    const int lane = tid & 31;
    const int wid  = tid >> 5;

    const int mxk = (int)(g_mm[0] ^ 0x80000000u);
    const int mnk = (int)((~g_mm[1]) ^ 0x80000000u);
    const int shift = mxk + mnk;

    // ---- setup: scores, flipped relevancy, gains (threads 0..255) ----
    float sj = 0.f, gain = 0.f; int e = 0;
    if (tid < 256) {
        sj = yp[b * N_DIM + tid];
        s[tid] = sj;
        e = shift - ytr[b * N_DIM + tid];
        e = min(max(e, 0), 30);
        ei[tid] = e;
        gain = (float)((1u << e) - 1u);
        gA[tid] = gain;
        u[tid] = 1.0f;
    }
    __syncthreads();

    // ---- B_mat[j] = sum_k |s_j - s_k| (Kahan) + IDCG via stable rank ----
    float idcg = 0.f;
    if (tid < 256) {
        float bsum = 0.f, bc = 0.f;
        int pos = 0;
        for (int k = 0; k < N_DIM; k++) {
            float d  = fabsf(sj - s[k]);
            float y  = d - bc;
            float t2 = bsum + y;
            bc = (t2 - bsum) - y;
            bsum = t2;
            int ek = ei[k];
            pos += (ek > e) ? 1 : 0;
            pos += ((k < tid) && (ek == e)) ? 1 : 0;
        }
        Bm[tid] = bsum;
        float x = gain / log2f((float)(pos + 2));
        for (int o = 16; o; o >>= 1) x += __shfl_xor_sync(0xffffffffu, x, o);
        if (lane == 0) red[wid] = x;
    }
    __syncthreads();   // publishes Bm[] and red[0..7]
    if (tid == 0) {
        for (int k = 0; k < 8; k++) idcg += red[k];   // kept in tid0's register
    }

    // ---- build P (fp16): row i = softmax_j(s_j*(255-2i) - Bm_j), tau=1 ----
    __half* Phh = (__half*)Ph;
    for (int i = wid; i < N_DIM; i += 16) {
        float sc = (float)(255 - 2 * i);
        float lg[8], ev[8];
        float mxl = -3.4e38f;
        #pragma unroll
        for (int k = 0; k < 8; k++) {
            int j = k * 32 + lane;
            float l = fmaf(s[j], sc, -Bm[j]);
            lg[k] = l;
            mxl = fmaxf(mxl, l);
        }
        for (int o = 16; o; o >>= 1) mxl = fmaxf(mxl, __shfl_xor_sync(0xffffffffu, mxl, o));
        float ssum = 0.f;
        #pragma unroll
        for (int k = 0; k < 8; k++) { float ex = expf(lg[k] - mxl); ev[k] = ex; ssum += ex; }
        for (int o = 16; o; o >>= 1) ssum += __shfl_xor_sync(0xffffffffu, ssum, o);
        float inv = 1.0f / ssum;
        __half* row = Phh + i * (2 * RSW);
        #pragma unroll
        for (int k = 0; k < 8; k++) row[k * 32 + lane] = __float2half_rn(ev[k] * inv);
    }
    __syncthreads();

    // ---- Sinkhorn with early exit ----
    const int p = tid & 127;                 // column pair (cols 2p, 2p+1)
    const int q = tid >> 7;                  // row quarter (64 rows)
    const unsigned* colp = Ph + (q * 64) * RSW + p;
    const float* uq = u + q * 64;
    const int ir = tid & 255;                // row for row pass
    const int h  = tid >> 8;                 // column half (128 cols)
    const unsigned* rowp = Ph + ir * RSW + h * 64;
    const float* vh = v + h * 128;
    float vprev = 0.f;

    for (int it = 0; it < ITERS; it++) {
        // column pass: partial over 64 rows for cols (2p, 2p+1)
        float a0 = 0.f, a1 = 0.f, a2 = 0.f, a3 = 0.f;
        #pragma unroll
        for (int i4 = 0; i4 < 16; i4++) {
            float4 uu = *(const float4*)(uq + 4 * i4);
            unsigned w0 = colp[(4 * i4 + 0) * RSW];
            unsigned w1 = colp[(4 * i4 + 1) * RSW];
            unsigned w2 = colp[(4 * i4 + 2) * RSW];
            unsigned w3 = colp[(4 * i4 + 3) * RSW];
            float2 f0 = __half22float2(*(__half2*)&w0);
            float2 f1 = __half22float2(*(__half2*)&w1);
            float2 f2 = __half22float2(*(__half2*)&w2);
            float2 f3 = __half22float2(*(__half2*)&w3);
            a0 = fmaf(f0.x, uu.x, a0); a1 = fmaf(f0.y, uu.x, a1);
            a2 = fmaf(f1.x, uu.y, a2); a3 = fmaf(f1.y, uu.y, a3);
            a0 = fmaf(f2.x, uu.z, a0); a1 = fmaf(f2.y, uu.z, a1);
            a2 = fmaf(f3.x, uu.w, a2); a3 = fmaf(f3.y, uu.w, a3);
        }
        ((float2*)(sp4 + q * 256))[p] = make_float2(a0 + a2, a1 + a3);
        __syncthreads();

        // v update + convergence flag (threads 0..255)
        int ch = 0;
        if (tid < 256) {
            float S = (sp4[tid] + sp4[256 + tid]) + (sp4[512 + tid] + sp4[768 + tid]);
            float vn = 1.0f / fmaxf(S, 1e-10f);
            v[tid] = vn;
            ch = (fabsf(vn - vprev) > 2e-6f * fabsf(vprev)) ? 1 : 0;
            vprev = vn;
        }
        if (__syncthreads_or(ch) == 0) break;   // fixed point: rest of iters inert

        // row pass: half-row dot with v
        float r0 = 0.f, r1 = 0.f, r2 = 0.f, r3 = 0.f;
        #pragma unroll
        for (int j4 = 0; j4 < 16; j4++) {
            float4 v0 = *(const float4*)(vh + 8 * j4);
            float4 v1 = *(const float4*)(vh + 8 * j4 + 4);
            unsigned w0 = rowp[4 * j4 + 0];
            unsigned w1 = rowp[4 * j4 + 1];
            unsigned w2 = rowp[4 * j4 + 2];
            unsigned w3 = rowp[4 * j4 + 3];
            float2 f0 = __half22float2(*(__half2*)&w0);
            float2 f1 = __half22float2(*(__half2*)&w1);
            float2 f2 = __half22float2(*(__half2*)&w2);
            float2 f3 = __half22float2(*(__half2*)&w3);
            r0 = fmaf(f0.x, v0.x, r0); r1 = fmaf(f0.y, v0.y, r1);
            r2 = fmaf(f1.x, v0.z, r2); r3 = fmaf(f1.y, v0.w, r3);
            r0 = fmaf(f2.x, v1.x, r0); r1 = fmaf(f2.y, v1.y, r1);
            r2 = fmaf(f3.x, v1.z, r2); r3 = fmaf(f3.y, v1.w, r3);
        }
        rp[tid] = (r0 + r1) + (r2 + r3);
        __syncthreads();

        if (tid < 256) u[tid] = 1.0f / fmaxf(rp[tid] + rp[256 + tid], 1e-10f);
        __syncthreads();
    }

    // ---- final: num = sum_i disc_i * u_i * (P[i] . (v*g)) ----
    if (tid < 256) w[tid] = v[tid] * gA[tid];
    __syncthreads();
    {
        float r0 = 0.f, r1 = 0.f, r2 = 0.f, r3 = 0.f;
        const float* wh = w + h * 128;
        #pragma unroll
        for (int j4 = 0; j4 < 16; j4++) {
            float4 v0 = *(const float4*)(wh + 8 * j4);
            float4 v1 = *(const float4*)(wh + 8 * j4 + 4);
            unsigned w0 = rowp[4 * j4 + 0];
            unsigned w1 = rowp[4 * j4 + 1];
            unsigned w2 = rowp[4 * j4 + 2];
            unsigned w3 = rowp[4 * j4 + 3];
            float2 f0 = __half22float2(*(__half2*)&w0);
            float2 f1 = __half22float2(*(__half2*)&w1);
            float2 f2 = __half22float2(*(__half2*)&w2);
            float2 f3 = __half22float2(*(__half2*)&w3);
            r0 = fmaf(f0.x, v0.x, r0); r1 = fmaf(f0.y, v0.y, r1);
            r2 = fmaf(f1.x, v0.z, r2); r3 = fmaf(f1.y, v0.w, r3);
            r0 = fmaf(f2.x, v1.x, r0); r1 = fmaf(f2.y, v1.y, r1);
            r2 = fmaf(f3.x, v1.z, r2); r3 = fmaf(f3.y, v1.w, r3);
        }
        rp[tid] = (r0 + r1) + (r2 + r3);
    }
    __syncthreads();
    if (tid < 256) {
        float val = u[tid] * (rp[tid] + rp[256 + tid]) / log2f((float)(tid + 2));
        for (int o = 16; o; o >>= 1) val += __shfl_xor_sync(0xffffffffu, val, o);
        if (lane == 0) red[wid] = val;
    }
    __syncthreads();
    if (tid == 0) {
        float num = 0.f;
        for (int k = 0; k < 8; k++) num += red[k];
        bool valid = (idcg != 0.0f);
        g_ndcg[b]  = valid ? (num / (idcg + 1e-10f)) : 0.0f;
        g_valid[b] = valid ? 1 : 0;
    }
}

// ---------------------------------------------------------------- finalize ---
__global__ void final_kernel(float* __restrict__ out) {
    int tid = threadIdx.x;           // 128 threads
    __shared__ float rs[4];
    __shared__ int   rc[4];
    float x = g_ndcg[tid];
    int   c = g_valid[tid];
    for (int o = 16; o; o >>= 1) {
        x += __shfl_xor_sync(0xffffffffu, x, o);
        c += __shfl_xor_sync(0xffffffffu, c, o);
    }
    int lane = tid & 31, wid = tid >> 5;
    if (lane == 0) { rs[wid] = x; rc[wid] = c; }
    __syncthreads();
    if (tid == 0) {
        float sum = 0.f; int cnt = 0;
        for (int k = 0; k < 4; k++) { sum += rs[k]; cnt += rc[k]; }
        out[0] = (cnt > 0) ? (-(sum / (float)cnt)) : 0.0f;
    }
}

// ------------------------------------------------------------------ launch ---
extern "C" void kernel_launch(void* const* d_in, const int* in_sizes, int n_in,
                              void* d_out, int out_size) {
    const float* yp  = (const float*)d_in[0];
    const int*   ytr = (const int*)d_in[1];
    float*       out = (float*)d_out;

    void* mm_addr = nullptr;
    cudaGetSymbolAddress(&mm_addr, g_mm);
    cudaMemsetAsync(mm_addr, 0, 2 * sizeof(unsigned));

    // P (256*129 words) + vectors (6*256) + sp4 (1024) + rp (512) + red (32) + ei (256)
    size_t smem = (size_t)(N_DIM * RSW + 6 * N_DIM + 4 * N_DIM + NTHR + 32 + N_DIM) * 4;
    cudaFuncSetAttribute(mega_kernel, cudaFuncAttributeMaxDynamicSharedMemorySize, (int)smem);

    minmax_kernel<<<32, 256>>>((const int4*)ytr);
    mega_kernel<<<B_DIM, NTHR, smem>>>(yp, ytr);
    final_kernel<<<1, 128>>>(out);
}

// round 4
// speedup vs baseline: 3.8842x; 1.0275x over previous
#include <cuda_runtime.h>
#include <cuda_bf16.h>

#define B_DIM 128
#define N_DIM 256
#define RSW   129                  // P row stride in 32-bit words (128 bf16x2 + 1 pad)
#define ITERS 50
#define NTHR  512

__device__ float g_ndcg[B_DIM];
__device__ int   g_valid[B_DIM];

// bf16 (stored in low/high 16 bits of a word) -> fp32, pure ALU ops
__device__ __forceinline__ float bf_lo(unsigned w) { return __int_as_float(w << 16); }
__device__ __forceinline__ float bf_hi(unsigned w) { return __int_as_float(w & 0xffff0000u); }

// ------------------------------------------------------------- mega kernel ---
// One CTA per batch, 512 threads. P stored bf16 in smem with padded rows.
// Sinkhorn on diagonal scalings (u,v); column pass thread-per-column-pair over a
// 64-row quarter; row pass thread-per-half-row. fp32 math, ALU-only unpack.
__global__ void __launch_bounds__(NTHR, 1)
mega_kernel(const float* __restrict__ yp, const int* __restrict__ ytr) {
    extern __shared__ unsigned smw[];
    unsigned* Ph = smw;                          // 256*129 words (bf16 P)
    float* s   = (float*)(Ph + N_DIM * RSW);
    float* Bm  = s   + N_DIM;
    float* gA  = Bm  + N_DIM;
    float* u   = gA  + N_DIM;
    float* v   = u   + N_DIM;
    float* w   = v   + N_DIM;
    float* sp4 = w   + N_DIM;                    // 1024 column partials (4 quarters)
    float* rp  = sp4 + 4 * N_DIM;                // 512 row partials
    float* red = rp  + NTHR;                     // 32 words (also minmax scratch)
    int*   ei  = (int*)(red + 32);               // 256
    int*   shf = ei + N_DIM;                     // 1 word

    const int tid  = threadIdx.x;
    const int b    = blockIdx.x;
    const int lane = tid & 31;
    const int wid  = tid >> 5;

    // ---- fused global min/max of y_true (each CTA scans all 128KB, L2-hot) ----
    {
        const int4* t4 = (const int4*)ytr;
        unsigned umx = 0u, umn = 0u;
        #pragma unroll
        for (int k = 0; k < (B_DIM * N_DIM / 4) / NTHR; k++) {
            int4 x = t4[tid + k * NTHR];
            unsigned u0 = (unsigned)x.x ^ 0x80000000u;
            unsigned u1 = (unsigned)x.y ^ 0x80000000u;
            unsigned u2 = (unsigned)x.z ^ 0x80000000u;
            unsigned u3 = (unsigned)x.w ^ 0x80000000u;
            umx = max(umx, max(max(u0, u1), max(u2, u3)));
            umn = max(umn, max(max(~u0, ~u1), max(~u2, ~u3)));
        }
        for (int o = 16; o; o >>= 1) {
            umx = max(umx, __shfl_xor_sync(0xffffffffu, umx, o));
            umn = max(umn, __shfl_xor_sync(0xffffffffu, umn, o));
        }
        unsigned* ur = (unsigned*)red;
        if (lane == 0) { ur[wid] = umx; ur[16 + wid] = umn; }
        __syncthreads();
        if (tid == 0) {
            for (int k = 1; k < 16; k++) { umx = max(umx, ur[k]); umn = max(umn, ur[16 + k]); }
            int mxv = (int)(umx ^ 0x80000000u);
            int mnv = (int)((~umn) ^ 0x80000000u);
            shf[0] = mxv + mnv;
        }
        __syncthreads();
    }
    const int shift = shf[0];

    // ---- setup: scores, flipped relevancy, gains (threads 0..255) ----
    float sj = 0.f, gain = 0.f; int e = 0;
    if (tid < 256) {
        sj = yp[b * N_DIM + tid];
        s[tid] = sj;
        e = shift - ytr[b * N_DIM + tid];
        e = min(max(e, 0), 30);
        ei[tid] = e;
        gain = (float)((1u << e) - 1u);
        gA[tid] = gain;
        u[tid] = 1.0f;
    }
    __syncthreads();

    // ---- B_mat[j] = sum_k |s_j - s_k| (Kahan) + IDCG via stable rank ----
    float idcg = 0.f;
    if (tid < 256) {
        float bsum = 0.f, bc = 0.f;
        int pos = 0;
        for (int k = 0; k < N_DIM; k++) {
            float d  = fabsf(sj - s[k]);
            float y  = d - bc;
            float t2 = bsum + y;
            bc = (t2 - bsum) - y;
            bsum = t2;
            int ek = ei[k];
            pos += (ek > e) ? 1 : 0;
            pos += ((k < tid) && (ek == e)) ? 1 : 0;
        }
        Bm[tid] = bsum;
        float x = gain / log2f((float)(pos + 2));
        for (int o = 16; o; o >>= 1) x += __shfl_xor_sync(0xffffffffu, x, o);
        if (lane == 0) red[wid] = x;
    }
    __syncthreads();
    if (tid == 0) {
        for (int k = 0; k < 8; k++) idcg += red[k];
    }

    // ---- build P (bf16): row i = softmax_j(s_j*(255-2i) - Bm_j), tau=1 ----
    __nv_bfloat16* Phb = (__nv_bfloat16*)Ph;
    for (int i = wid; i < N_DIM; i += 16) {
        float sc = (float)(255 - 2 * i);
        float lg[8], ev[8];
        float mxl = -3.4e38f;
        #pragma unroll
        for (int k = 0; k < 8; k++) {
            int j = k * 32 + lane;
            float l = fmaf(s[j], sc, -Bm[j]);
            lg[k] = l;
            mxl = fmaxf(mxl, l);
        }
        for (int o = 16; o; o >>= 1) mxl = fmaxf(mxl, __shfl_xor_sync(0xffffffffu, mxl, o));
        float ssum = 0.f;
        #pragma unroll
        for (int k = 0; k < 8; k++) { float ex = expf(lg[k] - mxl); ev[k] = ex; ssum += ex; }
        for (int o = 16; o; o >>= 1) ssum += __shfl_xor_sync(0xffffffffu, ssum, o);
        float inv = 1.0f / ssum;
        __nv_bfloat16* row = Phb + i * (2 * RSW);
        #pragma unroll
        for (int k = 0; k < 8; k++) row[k * 32 + lane] = __float2bfloat16_rn(ev[k] * inv);
    }
    __syncthreads();

    // ---- Sinkhorn with early exit ----
    const int p = tid & 127;                 // column pair (cols 2p, 2p+1)
    const int q = tid >> 7;                  // row quarter (64 rows)
    const unsigned* colp = Ph + (q * 64) * RSW + p;
    const float* uq = u + q * 64;
    const int ir = tid & 255;                // row for row pass
    const int h  = tid >> 8;                 // column half (128 cols)
    const unsigned* rowp = Ph + ir * RSW + h * 64;
    const float* vh = v + h * 128;
    float vprev = 0.f;

    for (int it = 0; it < ITERS; it++) {
        // column pass: partial over 64 rows for cols (2p, 2p+1)
        float a0 = 0.f, a1 = 0.f, a2 = 0.f, a3 = 0.f;
        #pragma unroll
        for (int i4 = 0; i4 < 16; i4++) {
            float4 uu = *(const float4*)(uq + 4 * i4);
            unsigned w0 = colp[(4 * i4 + 0) * RSW];
            unsigned w1 = colp[(4 * i4 + 1) * RSW];
            unsigned w2 = colp[(4 * i4 + 2) * RSW];
            unsigned w3 = colp[(4 * i4 + 3) * RSW];
            a0 = fmaf(bf_lo(w0), uu.x, a0); a1 = fmaf(bf_hi(w0), uu.x, a1);
            a2 = fmaf(bf_lo(w1), uu.y, a2); a3 = fmaf(bf_hi(w1), uu.y, a3);
            a0 = fmaf(bf_lo(w2), uu.z, a0); a1 = fmaf(bf_hi(w2), uu.z, a1);
            a2 = fmaf(bf_lo(w3), uu.w, a2); a3 = fmaf(bf_hi(w3), uu.w, a3);
        }
        ((float2*)(sp4 + q * 256))[p] = make_float2(a0 + a2, a1 + a3);
        __syncthreads();

        // v update + convergence flag (threads 0..255)
        int ch = 0;
        if (tid < 256) {
            float S = (sp4[tid] + sp4[256 + tid]) + (sp4[512 + tid] + sp4[768 + tid]);
            float vn = 1.0f / fmaxf(S, 1e-10f);
            v[tid] = vn;
            ch = (fabsf(vn - vprev) > 1e-5f * fabsf(vprev)) ? 1 : 0;
            vprev = vn;
        }
        if (__syncthreads_or(ch) == 0) break;   // fixed point: remaining iters inert

        // row pass: half-row dot with v
        float r0 = 0.f, r1 = 0.f, r2 = 0.f, r3 = 0.f;
        #pragma unroll
        for (int j4 = 0; j4 < 16; j4++) {
            float4 v0 = *(const float4*)(vh + 8 * j4);
            float4 v1 = *(const float4*)(vh + 8 * j4 + 4);
            unsigned w0 = rowp[4 * j4 + 0];
            unsigned w1 = rowp[4 * j4 + 1];
            unsigned w2 = rowp[4 * j4 + 2];
            unsigned w3 = rowp[4 * j4 + 3];
            r0 = fmaf(bf_lo(w0), v0.x, r0); r1 = fmaf(bf_hi(w0), v0.y, r1);
            r2 = fmaf(bf_lo(w1), v0.z, r2); r3 = fmaf(bf_hi(w1), v0.w, r3);
            r0 = fmaf(bf_lo(w2), v1.x, r0); r1 = fmaf(bf_hi(w2), v1.y, r1);
            r2 = fmaf(bf_lo(w3), v1.z, r2); r3 = fmaf(bf_hi(w3), v1.w, r3);
        }
        rp[tid] = (r0 + r1) + (r2 + r3);
        __syncthreads();

        if (tid < 256) u[tid] = 1.0f / fmaxf(rp[tid] + rp[256 + tid], 1e-10f);
        __syncthreads();
    }

    // ---- final: num = sum_i disc_i * u_i * (P[i] . (v*g)) ----
    if (tid < 256) w[tid] = v[tid] * gA[tid];
    __syncthreads();
    {
        float r0 = 0.f, r1 = 0.f, r2 = 0.f, r3 = 0.f;
        const float* wh = w + h * 128;
        #pragma unroll
        for (int j4 = 0; j4 < 16; j4++) {
            float4 v0 = *(const float4*)(wh + 8 * j4);
            float4 v1 = *(const float4*)(wh + 8 * j4 + 4);
            unsigned w0 = rowp[4 * j4 + 0];
            unsigned w1 = rowp[4 * j4 + 1];
            unsigned w2 = rowp[4 * j4 + 2];
            unsigned w3 = rowp[4 * j4 + 3];
            r0 = fmaf(bf_lo(w0), v0.x, r0); r1 = fmaf(bf_hi(w0), v0.y, r1);
            r2 = fmaf(bf_lo(w1), v0.z, r2); r3 = fmaf(bf_hi(w1), v0.w, r3);
            r0 = fmaf(bf_lo(w2), v1.x, r0); r1 = fmaf(bf_hi(w2), v1.y, r1);
            r2 = fmaf(bf_lo(w3), v1.z, r2); r3 = fmaf(bf_hi(w3), v1.w, r3);
        }
        rp[tid] = (r0 + r1) + (r2 + r3);
    }
    __syncthreads();
    if (tid < 256) {
        float val = u[tid] * (rp[tid] + rp[256 + tid]) / log2f((float)(tid + 2));
        for (int o = 16; o; o >>= 1) val += __shfl_xor_sync(0xffffffffu, val, o);
        if (lane == 0) red[wid] = val;
    }
    __syncthreads();
    if (tid == 0) {
        float num = 0.f;
        for (int k = 0; k < 8; k++) num += red[k];
        bool valid = (idcg != 0.0f);
        g_ndcg[b]  = valid ? (num / (idcg + 1e-10f)) : 0.0f;
        g_valid[b] = valid ? 1 : 0;
    }
}

// ---------------------------------------------------------------- finalize ---
__global__ void final_kernel(float* __restrict__ out) {
    int tid = threadIdx.x;           // 128 threads
    __shared__ float rs[4];
    __shared__ int   rc[4];
    float x = g_ndcg[tid];
    int   c = g_valid[tid];
    for (int o = 16; o; o >>= 1) {
        x += __shfl_xor_sync(0xffffffffu, x, o);
        c += __shfl_xor_sync(0xffffffffu, c, o);
    }
    int lane = tid & 31, wid = tid >> 5;
    if (lane == 0) { rs[wid] = x; rc[wid] = c; }
    __syncthreads();
    if (tid == 0) {
        float sum = 0.f; int cnt = 0;
        for (int k = 0; k < 4; k++) { sum += rs[k]; cnt += rc[k]; }
        out[0] = (cnt > 0) ? (-(sum / (float)cnt)) : 0.0f;
    }
}

// ------------------------------------------------------------------ launch ---
extern "C" void kernel_launch(void* const* d_in, const int* in_sizes, int n_in,
                              void* d_out, int out_size) {
    const float* yp  = (const float*)d_in[0];
    const int*   ytr = (const int*)d_in[1];
    float*       out = (float*)d_out;

    // P + 6 vectors + sp4 + rp + red + ei + shf(pad 8)
    size_t smem = (size_t)(N_DIM * RSW + 6 * N_DIM + 4 * N_DIM + NTHR + 32 + N_DIM + 8) * 4;
    cudaFuncSetAttribute(mega_kernel, cudaFuncAttributeMaxDynamicSharedMemorySize, (int)smem);

    mega_kernel<<<B_DIM, NTHR, smem>>>(yp, ytr);
    final_kernel<<<1, 128>>>(out);
}